// round 4
// baseline (speedup 1.0000x reference)
#include <cuda_runtime.h>
#include <math.h>

#define B 8
#define S 1024
#define D 768
#define BS (B*S)          // 8192
#define HEADS 8
#define DH 96
#define L_LAYERS 3
#define KNN 5

// ---------------- scratch (static device globals; no runtime alloc) ----------------
__device__ float g_S[(size_t)B*HEADS*S*S];    // 256MB: sim (first 32MB) then attn scores
__device__ float g_H[BS*D];
__device__ float g_XG[BS*D];
__device__ float g_GCN[BS*D];
__device__ float g_QKV[(size_t)BS*3*D];
__device__ float g_O[BS*D];
__device__ float g_ATT[BS*D];
__device__ float g_CAT[(size_t)BS*2*D];
__device__ float g_FUSED[BS*D];
__device__ unsigned g_adj[BS*32];             // bitmask adjacency, 32 words/row
__device__ float g_dinv[BS];
__device__ int   g_topk[BS*KNN];

// =====================================================================
// Generic GEMM: C[M,N] = A[M,K] @ B[K,N] (+bias). EPI=1: sigmoid gate fuse.
// BM=BN=128, BK=16, 256 threads, 8x8 per thread. M%128==0, N%128==0, K%16==0.
// =====================================================================
template<int EPI>
__global__ __launch_bounds__(256)
void gemm128(const float* __restrict__ A, const float* __restrict__ Bm,
             const float* __restrict__ bias, float* __restrict__ C,
             int M, int N, int K,
             const float* __restrict__ e_gcn, const float* __restrict__ e_att)
{
    __shared__ float As[16][132];
    __shared__ float Bs[16][132];
    const int bm = blockIdx.y * 128, bn = blockIdx.x * 128;
    const int t = threadIdx.x;
    const int tx = t & 15, ty = t >> 4;
    float acc[8][8];
    #pragma unroll
    for (int i = 0; i < 8; i++)
        #pragma unroll
        for (int j = 0; j < 8; j++) acc[i][j] = 0.f;

    for (int k0 = 0; k0 < K; k0 += 16) {
        #pragma unroll
        for (int i = 0; i < 2; i++) {
            int f4 = t + i*256;
            int row = f4 >> 2, kc = (f4 & 3) * 4;
            float4 v = *(const float4*)(A + (size_t)(bm + row)*K + k0 + kc);
            As[kc+0][row] = v.x; As[kc+1][row] = v.y;
            As[kc+2][row] = v.z; As[kc+3][row] = v.w;
        }
        #pragma unroll
        for (int i = 0; i < 2; i++) {
            int f4 = t + i*256;
            int kk = f4 >> 5, nc = (f4 & 31) * 4;
            float4 v = *(const float4*)(Bm + (size_t)(k0 + kk)*N + bn + nc);
            *(float4*)&Bs[kk][nc] = v;
        }
        __syncthreads();
        #pragma unroll
        for (int kk = 0; kk < 16; kk++) {
            float a[8], b[8];
            #pragma unroll
            for (int i = 0; i < 8; i++) a[i] = As[kk][ty*8 + i];
            #pragma unroll
            for (int j = 0; j < 8; j++) b[j] = Bs[kk][tx*8 + j];
            #pragma unroll
            for (int i = 0; i < 8; i++)
                #pragma unroll
                for (int j = 0; j < 8; j++)
                    acc[i][j] += a[i] * b[j];
        }
        __syncthreads();
    }
    #pragma unroll
    for (int i = 0; i < 8; i++) {
        int row = bm + ty*8 + i;
        #pragma unroll
        for (int j = 0; j < 8; j++) {
            int col = bn + tx*8 + j;
            float v = acc[i][j];
            if (bias) v += bias[col];
            size_t off = (size_t)row * N + col;
            if (EPI == 1) {
                float g = 1.f / (1.f + expf(-v));
                v = g * e_gcn[off] + (1.f - g) * e_att[off];
            }
            C[off] = v;
        }
    }
}

// =====================================================================
// Dot kernel: C[z][m][n] = scale * sum_k A[m,k]*B[n,k]  (A,B row-major [*,K])
// M=N=1024 fixed, 128x128 tile, BK=16, batched over z (z -> (zb,zh) via HZ).
// =====================================================================
__global__ __launch_bounds__(256)
void dot_kernel(const float* __restrict__ Ab, const float* __restrict__ Bb,
                float* __restrict__ Cb, int K, int lda, int ldb,
                long long aZb, long long aZh, long long bZb, long long bZh,
                int HZ, float scale)
{
    const int z = blockIdx.z;
    const int zb = z / HZ, zh = z - zb * HZ;
    const float* A = Ab + (size_t)zb*aZb + (size_t)zh*aZh;
    const float* Bp = Bb + (size_t)zb*bZb + (size_t)zh*bZh;
    float* C = Cb + (size_t)z * S * S;
    const int bm = blockIdx.y * 128, bn = blockIdx.x * 128;
    const int t = threadIdx.x;
    const int tx = t & 15, ty = t >> 4;
    __shared__ float As[16][132];
    __shared__ float Bs[16][132];
    float acc[8][8];
    #pragma unroll
    for (int i = 0; i < 8; i++)
        #pragma unroll
        for (int j = 0; j < 8; j++) acc[i][j] = 0.f;

    for (int k0 = 0; k0 < K; k0 += 16) {
        #pragma unroll
        for (int i = 0; i < 2; i++) {
            int f4 = t + i*256;
            int row = f4 >> 2, kc = (f4 & 3) * 4;
            float4 v = *(const float4*)(A + (size_t)(bm + row)*lda + k0 + kc);
            As[kc+0][row] = v.x; As[kc+1][row] = v.y;
            As[kc+2][row] = v.z; As[kc+3][row] = v.w;
            float4 w = *(const float4*)(Bp + (size_t)(bn + row)*ldb + k0 + kc);
            Bs[kc+0][row] = w.x; Bs[kc+1][row] = w.y;
            Bs[kc+2][row] = w.z; Bs[kc+3][row] = w.w;
        }
        __syncthreads();
        #pragma unroll
        for (int kk = 0; kk < 16; kk++) {
            float a[8], b[8];
            #pragma unroll
            for (int i = 0; i < 8; i++) a[i] = As[kk][ty*8 + i];
            #pragma unroll
            for (int j = 0; j < 8; j++) b[j] = Bs[kk][tx*8 + j];
            #pragma unroll
            for (int i = 0; i < 8; i++)
                #pragma unroll
                for (int j = 0; j < 8; j++)
                    acc[i][j] += a[i] * b[j];
        }
        __syncthreads();
    }
    #pragma unroll
    for (int i = 0; i < 8; i++)
        #pragma unroll
        for (int j = 0; j < 8; j++)
            C[(size_t)(bm + ty*8 + i) * S + bn + tx*8 + j] = acc[i][j] * scale;
}

// =====================================================================
// AV kernel: O[b, i, h*96+d] = sum_j P[z][i][j] * V[b,j,h*96+d]
// BM=128, BN=96, BK=32. grid (i_tiles=8, z=64), 256 threads, 8x6 per thread.
// =====================================================================
__global__ __launch_bounds__(256)
void av_kernel(const float* __restrict__ P, const float* __restrict__ qkv,
               float* __restrict__ O)
{
    const int z = blockIdx.y;
    const int b = z >> 3, h = z & 7;
    const float* Pz = P + (size_t)z * S * S;
    const float* V = qkv + (size_t)b * S * (3*D) + 2*D + h*DH;
    float* Ob = O + (size_t)b * S * D + h*DH;
    const int i0 = blockIdx.x * 128;
    __shared__ float Ps[32][132];
    __shared__ float Vs[32][100];
    const int t = threadIdx.x;
    const int tx = t & 15, ty = t >> 4;
    float acc[8][6];
    #pragma unroll
    for (int i = 0; i < 8; i++)
        #pragma unroll
        for (int j = 0; j < 6; j++) acc[i][j] = 0.f;

    for (int j0 = 0; j0 < S; j0 += 32) {
        #pragma unroll
        for (int i = 0; i < 4; i++) {
            int f4 = t + i*256;
            int row = f4 >> 3, jc = (f4 & 7) * 4;
            float4 v = *(const float4*)(Pz + (size_t)(i0 + row)*S + j0 + jc);
            Ps[jc+0][row] = v.x; Ps[jc+1][row] = v.y;
            Ps[jc+2][row] = v.z; Ps[jc+3][row] = v.w;
        }
        #pragma unroll
        for (int i = 0; i < 3; i++) {
            int f4 = t + i*256;
            int row = f4 / 24, dc = (f4 % 24) * 4;
            float4 v = *(const float4*)(V + (size_t)(j0 + row)*(3*D) + dc);
            *(float4*)&Vs[row][dc] = v;
        }
        __syncthreads();
        #pragma unroll
        for (int kk = 0; kk < 32; kk++) {
            float a[8], bb[6];
            #pragma unroll
            for (int i = 0; i < 8; i++) a[i] = Ps[kk][ty*8 + i];
            #pragma unroll
            for (int j = 0; j < 6; j++) bb[j] = Vs[kk][tx*6 + j];
            #pragma unroll
            for (int i = 0; i < 8; i++)
                #pragma unroll
                for (int j = 0; j < 6; j++)
                    acc[i][j] += a[i] * bb[j];
        }
        __syncthreads();
    }
    #pragma unroll
    for (int i = 0; i < 8; i++)
        #pragma unroll
        for (int j = 0; j < 6; j++)
            Ob[(size_t)(i0 + ty*8 + i) * D + tx*6 + j] = acc[i][j];
}

// ---------------- softmax over rows of 1024 ----------------
__global__ __launch_bounds__(256)
void softmax_kernel(float* __restrict__ s)
{
    const int t = threadIdx.x;
    float* row = s + (size_t)blockIdx.x * S;
    __shared__ float red[256];
    float v[4];
    float mx = -3.4e38f;
    #pragma unroll
    for (int i = 0; i < 4; i++) { v[i] = row[t + i*256]; mx = fmaxf(mx, v[i]); }
    red[t] = mx; __syncthreads();
    for (int o = 128; o > 0; o >>= 1) { if (t < o) red[t] = fmaxf(red[t], red[t+o]); __syncthreads(); }
    mx = red[0]; __syncthreads();
    float sum = 0.f;
    #pragma unroll
    for (int i = 0; i < 4; i++) { v[i] = expf(v[i] - mx); sum += v[i]; }
    red[t] = sum; __syncthreads();
    for (int o = 128; o > 0; o >>= 1) { if (t < o) red[t] += red[t+o]; __syncthreads(); }
    float inv = 1.f / red[0];
    #pragma unroll
    for (int i = 0; i < 4; i++) row[t + i*256] = v[i] * inv;
}

// ---------------- top-k (k=5), strict > keeps earliest index on ties ----------------
__global__ void topk_kernel(const float* __restrict__ sim, int* __restrict__ topk)
{
    int r = blockIdx.x * blockDim.x + threadIdx.x;
    if (r >= BS) return;
    const float* row = sim + (size_t)r * S;
    float tv[KNN]; int ti[KNN];
    #pragma unroll
    for (int p = 0; p < KNN; p++) { tv[p] = -3.4e38f; ti[p] = 0; }
    for (int j = 0; j < S; j++) {
        float v = row[j];
        if (v > tv[KNN-1]) {
            int p = KNN - 1;
            while (p > 0 && v > tv[p-1]) { tv[p] = tv[p-1]; ti[p] = ti[p-1]; p--; }
            tv[p] = v; ti[p] = j;
        }
    }
    #pragma unroll
    for (int p = 0; p < KNN; p++) topk[r*KNN + p] = ti[p];
}

// ---------------- scatter bitmask adjacency (symmetrize + self loops) ----------------
__global__ void scatter_kernel(const int* __restrict__ topk, unsigned* __restrict__ adj)
{
    int r = blockIdx.x * blockDim.x + threadIdx.x;
    if (r >= BS) return;
    int b = r >> 10, i = r & 1023;
    unsigned* base = adj + (size_t)b * S * 32;
    atomicOr(&base[i*32 + (i >> 5)], 1u << (i & 31));
    #pragma unroll
    for (int p = 0; p < KNN; p++) {
        int j = topk[r*KNN + p];
        atomicOr(&base[i*32 + (j >> 5)], 1u << (j & 31));
        atomicOr(&base[j*32 + (i >> 5)], 1u << (i & 31));
    }
}

__global__ void deg_kernel(const unsigned* __restrict__ adj, float* __restrict__ dinv)
{
    int r = blockIdx.x * blockDim.x + threadIdx.x;
    if (r >= BS) return;
    int cnt = 0;
    #pragma unroll
    for (int w = 0; w < 32; w++) cnt += __popc(adj[r*32 + w]);
    dinv[r] = rsqrtf((float)cnt);
}

// ---------------- sparse GCN aggregation: out = D^-1/2 A D^-1/2 (XG) + bias ----------------
__global__ __launch_bounds__(256)
void gcn_agg(const float* __restrict__ xg, const unsigned* __restrict__ adj,
             const float* __restrict__ dinv, const float* __restrict__ bias,
             float* __restrict__ out)
{
    const int r = blockIdx.x;
    const int t = threadIdx.x;
    const int b = r >> 10;
    const float di = dinv[r];
    float a0 = 0.f, a1 = 0.f, a2 = 0.f;
    for (int w = 0; w < 32; w++) {
        unsigned m = adj[r*32 + w];
        while (m) {
            int bit = __ffs(m) - 1; m &= m - 1;
            int j = (b << 10) + (w << 5) + bit;
            float c = di * dinv[j];
            const float* xr = xg + (size_t)j * D;
            a0 += c * xr[t]; a1 += c * xr[t + 256]; a2 += c * xr[t + 512];
        }
    }
    float* o = out + (size_t)r * D;
    o[t]       = a0 + bias[t];
    o[t + 256] = a1 + bias[t + 256];
    o[t + 512] = a2 + bias[t + 512];
}

// ---------------- concat [GCN | ATT] ----------------
__global__ void concat_kernel(const float* __restrict__ g, const float* __restrict__ a,
                              float* __restrict__ c)
{
    size_t idx = (size_t)blockIdx.x * 256 + threadIdx.x;
    size_t row = idx / (2*D);
    int col = (int)(idx - row * (2*D));
    c[idx] = (col < D) ? g[row*D + col] : a[row*D + col - D];
}

// ---------------- LayerNorm(fused + h) -> h ----------------
__global__ __launch_bounds__(256)
void ln_kernel(const float* __restrict__ fused, float* __restrict__ h,
               const float* __restrict__ scale, const float* __restrict__ bias)
{
    const int r = blockIdx.x, t = threadIdx.x;
    __shared__ float red[256];
    const size_t base = (size_t)r * D;
    float v0 = fused[base + t]       + h[base + t];
    float v1 = fused[base + t + 256] + h[base + t + 256];
    float v2 = fused[base + t + 512] + h[base + t + 512];
    red[t] = v0 + v1 + v2; __syncthreads();
    for (int o = 128; o > 0; o >>= 1) { if (t < o) red[t] += red[t+o]; __syncthreads(); }
    float mu = red[0] * (1.f / D); __syncthreads();
    float d0 = v0 - mu, d1 = v1 - mu, d2 = v2 - mu;
    red[t] = d0*d0 + d1*d1 + d2*d2; __syncthreads();
    for (int o = 128; o > 0; o >>= 1) { if (t < o) red[t] += red[t+o]; __syncthreads(); }
    float rs = rsqrtf(red[0] * (1.f / D) + 1e-5f);
    h[base + t]       = d0 * rs * scale[t]       + bias[t];
    h[base + t + 256] = d1 * rs * scale[t + 256] + bias[t + 256];
    h[base + t + 512] = d2 * rs * scale[t + 512] + bias[t + 512];
}

// =====================================================================
extern "C" void kernel_launch(void* const* d_in, const int* in_sizes, int n_in,
                              void* d_out, int out_size)
{
    const float* x      = (const float*)d_in[0];
    const float* gcn_w  = (const float*)d_in[1];
    const float* gcn_b  = (const float*)d_in[2];
    const float* ain_w  = (const float*)d_in[3];
    const float* ain_b  = (const float*)d_in[4];
    const float* aout_w = (const float*)d_in[5];
    const float* aout_b = (const float*)d_in[6];
    const float* gate_w = (const float*)d_in[7];
    const float* gate_b = (const float*)d_in[8];
    const float* ln_s   = (const float*)d_in[9];
    const float* ln_b   = (const float*)d_in[10];
    const float* proj_w = (const float*)d_in[11];
    const float* proj_b = (const float*)d_in[12];
    float* out = (float*)d_out;

    float *Sb, *H, *XG, *GCN, *QKV, *O, *ATT, *CAT, *FUSED, *DINV;
    unsigned* ADJ; int* TOPK;
    cudaGetSymbolAddress((void**)&Sb,    g_S);
    cudaGetSymbolAddress((void**)&H,     g_H);
    cudaGetSymbolAddress((void**)&XG,    g_XG);
    cudaGetSymbolAddress((void**)&GCN,   g_GCN);
    cudaGetSymbolAddress((void**)&QKV,   g_QKV);
    cudaGetSymbolAddress((void**)&O,     g_O);
    cudaGetSymbolAddress((void**)&ATT,   g_ATT);
    cudaGetSymbolAddress((void**)&CAT,   g_CAT);
    cudaGetSymbolAddress((void**)&FUSED, g_FUSED);
    cudaGetSymbolAddress((void**)&DINV,  g_dinv);
    cudaGetSymbolAddress((void**)&ADJ,   g_adj);
    cudaGetSymbolAddress((void**)&TOPK,  g_topk);

    cudaMemsetAsync(ADJ, 0, (size_t)BS*32*sizeof(unsigned), 0);
    cudaMemcpyAsync(H, x, (size_t)BS*D*sizeof(float), cudaMemcpyDeviceToDevice, 0);

    // --- graph construction (once, from x) ---
    // sim = x x^T per batch
    dot_kernel<<<dim3(8, 8, B), 256>>>(x, x, Sb, D, D, D,
                                       (long long)S*D, 0, (long long)S*D, 0, 1, 1.0f);
    topk_kernel<<<BS/256, 256>>>(Sb, TOPK);
    scatter_kernel<<<BS/256, 256>>>(TOPK, ADJ);
    deg_kernel<<<BS/256, 256>>>(ADJ, DINV);

    const float att_scale = 1.0f / sqrtf((float)DH);

    for (int l = 0; l < L_LAYERS; l++) {
        const float* gw  = gcn_w  + (size_t)l*D*D;
        const float* gb  = gcn_b  + (size_t)l*D;
        const float* aiw = ain_w  + (size_t)l*D*3*D;
        const float* aib = ain_b  + (size_t)l*3*D;
        const float* aow = aout_w + (size_t)l*D*D;
        const float* aob = aout_b + (size_t)l*D;
        const float* gtw = gate_w + (size_t)l*2*D*D;
        const float* gtb = gate_b + (size_t)l*D;

        // GCN branch
        gemm128<0><<<dim3(D/128, BS/128), 256>>>(H, gw, nullptr, XG, BS, D, D, nullptr, nullptr);
        gcn_agg<<<BS, 256>>>(XG, ADJ, DINV, gb, GCN);

        // Attention branch
        gemm128<0><<<dim3(3*D/128, BS/128), 256>>>(H, aiw, aib, QKV, BS, 3*D, D, nullptr, nullptr);
        dot_kernel<<<dim3(8, 8, B*HEADS), 256>>>(QKV, QKV + D, Sb, DH, 3*D, 3*D,
                                                 (long long)S*3*D, DH,
                                                 (long long)S*3*D, DH,
                                                 HEADS, att_scale);
        softmax_kernel<<<B*HEADS*S, 256>>>(Sb);
        av_kernel<<<dim3(8, B*HEADS), 256>>>(Sb, QKV, O);
        gemm128<0><<<dim3(D/128, BS/128), 256>>>(O, aow, aob, ATT, BS, D, D, nullptr, nullptr);

        // Gate + fuse (fused epilogue), then LN residual
        concat_kernel<<<(int)(((size_t)BS*2*D)/256), 256>>>(GCN, ATT, CAT);
        gemm128<1><<<dim3(D/128, BS/128), 256>>>(CAT, gtw, gtb, FUSED, BS, D, 2*D, GCN, ATT);
        ln_kernel<<<BS, 256>>>(FUSED, H, ln_s + (size_t)l*D, ln_b + (size_t)l*D);
    }

    // final projection -> d_out
    gemm128<0><<<dim3(D/128, BS/128), 256>>>(H, proj_w, proj_b, out, BS, D, D, nullptr, nullptr);
}

// round 12
// speedup vs baseline: 1.7164x; 1.7164x over previous
#include <cuda_runtime.h>
#include <cuda_bf16.h>
#include <math.h>
#include <stdint.h>

#define B 8
#define S 1024
#define D 768
#define BS (B*S)          // 8192
#define HEADS 8
#define DH 96
#define L_LAYERS 3
#define KNN 5
#define ZN (B*HEADS)      // 64

typedef __nv_bfloat16 bf16;

// ---------------- scratch (static device globals; no runtime alloc) ----------------
__device__ float g_S[(size_t)ZN*S*S];                 // 256MB fp32: sim (first 32MB) then scores
__device__ bf16  g_Phi[(size_t)ZN*S*S];
__device__ bf16  g_Plo[(size_t)ZN*S*S];
__device__ float g_H[BS*D];
__device__ float g_XG[BS*D];
__device__ float g_GCN[BS*D];
__device__ float g_QKV[(size_t)BS*3*D];
__device__ float g_O[BS*D];
__device__ float g_ATT[BS*D];
__device__ float g_FUSED[BS*D];
__device__ bf16  g_Hhi[BS*D],  g_Hlo[BS*D];
__device__ bf16  g_QKVhi[(size_t)BS*3*D], g_QKVlo[(size_t)BS*3*D];
__device__ bf16  g_Ohi[BS*D],  g_Olo[BS*D];
__device__ bf16  g_CAThi[(size_t)BS*2*D], g_CATlo[(size_t)BS*2*D];
__device__ bf16  g_VThi[(size_t)ZN*DH*S], g_VTlo[(size_t)ZN*DH*S];
__device__ bf16  g_WGhi[D*D],      g_WGlo[D*D];
__device__ bf16  g_WAIhi[3*D*D],   g_WAIlo[3*D*D];
__device__ bf16  g_WAOhi[D*D],     g_WAOlo[D*D];
__device__ bf16  g_WGThi[2*D*D],   g_WGTlo[2*D*D];
__device__ bf16  g_WPhi[D*D],      g_WPlo[D*D];
__device__ unsigned g_adj[BS*32];
__device__ float g_dinv[BS];
__device__ int   g_topk[BS*KNN];

// ====================== helpers (baseline PTX only: cp.async / ldmatrix / mma.sync) ======================
__device__ __forceinline__ uint32_t smem_u32(const void* p) {
    uint32_t a;
    asm("{ .reg .u64 t; cvta.to.shared.u64 t, %1; cvt.u32.u64 %0, t; }" : "=r"(a) : "l"(p));
    return a;
}
__device__ __forceinline__ void cpasync16(uint32_t sdst, const void* gsrc) {
    asm volatile("cp.async.cg.shared.global [%0], [%1], 16;" :: "r"(sdst), "l"(gsrc) : "memory");
}
__device__ __forceinline__ void ldsm4(uint32_t& r0, uint32_t& r1, uint32_t& r2, uint32_t& r3, uint32_t addr) {
    asm volatile("ldmatrix.sync.aligned.m8n8.x4.shared.b16 {%0,%1,%2,%3}, [%4];"
                 : "=r"(r0), "=r"(r1), "=r"(r2), "=r"(r3) : "r"(addr));
}
__device__ __forceinline__ void mma16816(float* c, const uint32_t* a, const uint32_t* b) {
    asm volatile("mma.sync.aligned.m16n8k16.row.col.f32.bf16.bf16.f32 "
                 "{%0,%1,%2,%3}, {%4,%5,%6,%7}, {%8,%9}, {%0,%1,%2,%3};"
                 : "+f"(c[0]), "+f"(c[1]), "+f"(c[2]), "+f"(c[3])
                 : "r"(a[0]), "r"(a[1]), "r"(a[2]), "r"(a[3]), "r"(b[0]), "r"(b[1]));
}

// =====================================================================
// fp32 SIMT dot kernel for sim (graph needs fp32-exact values for top-k):
// C[z][m][n] = sum_k A[m,k]*B[n,k]; M=N=1024, 128x128 tile, BK=16.
// =====================================================================
__global__ __launch_bounds__(256)
void dot_kernel(const float* __restrict__ Ab, float* __restrict__ Cb, int K)
{
    const int z = blockIdx.z;
    const float* A = Ab + (size_t)z * S * K;
    float* C = Cb + (size_t)z * S * S;
    const int bm = blockIdx.y * 128, bn = blockIdx.x * 128;
    const int t = threadIdx.x;
    const int tx = t & 15, ty = t >> 4;
    __shared__ float As[16][132];
    __shared__ float Bs[16][132];
    float acc[8][8];
    #pragma unroll
    for (int i = 0; i < 8; i++)
        #pragma unroll
        for (int j = 0; j < 8; j++) acc[i][j] = 0.f;

    for (int k0 = 0; k0 < K; k0 += 16) {
        #pragma unroll
        for (int i = 0; i < 2; i++) {
            int f4 = t + i*256;
            int row = f4 >> 2, kc = (f4 & 3) * 4;
            float4 v = *(const float4*)(A + (size_t)(bm + row)*K + k0 + kc);
            As[kc+0][row] = v.x; As[kc+1][row] = v.y;
            As[kc+2][row] = v.z; As[kc+3][row] = v.w;
            float4 w = *(const float4*)(A + (size_t)(bn + row)*K + k0 + kc);
            Bs[kc+0][row] = w.x; Bs[kc+1][row] = w.y;
            Bs[kc+2][row] = w.z; Bs[kc+3][row] = w.w;
        }
        __syncthreads();
        #pragma unroll
        for (int kk = 0; kk < 16; kk++) {
            float a[8], b[8];
            #pragma unroll
            for (int i = 0; i < 8; i++) a[i] = As[kk][ty*8 + i];
            #pragma unroll
            for (int j = 0; j < 8; j++) b[j] = Bs[kk][tx*8 + j];
            #pragma unroll
            for (int i = 0; i < 8; i++)
                #pragma unroll
                for (int j = 0; j < 8; j++)
                    acc[i][j] += a[i] * b[j];
        }
        __syncthreads();
    }
    #pragma unroll
    for (int i = 0; i < 8; i++)
        #pragma unroll
        for (int j = 0; j < 8; j++)
            C[(size_t)(bm + ty*8 + i) * S + bn + tx*8 + j] = acc[i][j];
}

// =====================================================================
// Split-bf16 HMMA GEMM: C[z][m][n] = alpha * sum_k A[m,k]*B[n,k] (+bias / gate)
// A: [M,K] lda;  B: [N,K] ldb (both K-major, bf16 hi/lo pairs)
// BM=128, BN (128 or 96), BK=32, 3-stage cp.async pipeline.
// Warp grid 2 x WN, warp tile 64x32. Rows padded to 80B (conflict-free ldmatrix).
// 3 passes folded into k loop: Ahi*Bhi + Ahi*Blo + Alo*Bhi.
// =====================================================================
template<int BN, int WN, int EPI>
__global__ void __launch_bounds__(256)
hmma_gemm(const bf16* __restrict__ Ahi, const bf16* __restrict__ Alo,
          const bf16* __restrict__ Bhi, const bf16* __restrict__ Blo,
          float* __restrict__ C, int K, int lda, int ldb, int ldc,
          long long aZb, long long aZh, long long bZb, long long bZh,
          long long cZb, long long cZh, int HZ,
          float alpha, const float* __restrict__ bias,
          const float* __restrict__ e_gcn, const float* __restrict__ e_att)
{
    extern __shared__ char smem[];
    constexpr int NTH = 64 * WN;            // 256 or 192 threads
    constexpr int ABYTES = 128 * 80;        // 128 rows x 32 bf16 padded to 40
    constexpr int BBYTES = BN * 80;
    constexpr int STB = ABYTES + BBYTES;
    const uint32_t sbase = smem_u32(smem);
    const int t = threadIdx.x, lane = t & 31, wid = t >> 5;
    const int wm = wid / WN, wn = wid % WN;

    const int z = blockIdx.z;
    const int zb = z / HZ, zh = z - zb * HZ;
    const bf16* Ah = Ahi + zb*aZb + zh*aZh;
    const bf16* Al = Alo + zb*aZb + zh*aZh;
    const bf16* Bh = Bhi + zb*bZb + zh*bZh;
    const bf16* Bl = Blo + zb*bZb + zh*bZh;
    float* Cz = C + zb*cZb + zh*cZh;
    const int bm = blockIdx.y * 128, bn = blockIdx.x * BN;

    const int CPP = K >> 5;                 // chunks (BK=32) per pass
    const int NC = 3 * CPP;

    auto issue = [&](int c) {
        const int p = c / CPP, kk = c - p*CPP;
        const bf16* Ap = (p == 2) ? Al : Ah;
        const bf16* Bp = (p == 1) ? Bl : Bh;
        const int st = c % 3, k0 = kk * 32;
        const uint32_t sA = sbase + st*STB, sB = sA + ABYTES;
        for (int i = t; i < 512; i += NTH) {
            int row = i >> 2, ch = i & 3;
            cpasync16(sA + row*80 + ch*16, Ap + (size_t)(bm + row)*lda + k0 + ch*8);
        }
        for (int i = t; i < BN*4; i += NTH) {
            int row = i >> 2, ch = i & 3;
            cpasync16(sB + row*80 + ch*16, Bp + (size_t)(bn + row)*ldb + k0 + ch*8);
        }
        asm volatile("cp.async.commit_group;" ::: "memory");
    };

    float acc[4][4][4];
    #pragma unroll
    for (int i = 0; i < 4; i++)
        #pragma unroll
        for (int j = 0; j < 4; j++)
            #pragma unroll
            for (int e = 0; e < 4; e++) acc[i][j][e] = 0.f;

    issue(0);
    if (NC > 1) issue(1);

    for (int c = 0; c < NC; c++) {
        if (c + 1 < NC) asm volatile("cp.async.wait_group 1;" ::: "memory");
        else            asm volatile("cp.async.wait_group 0;" ::: "memory");
        __syncthreads();
        if (c + 2 < NC) issue(c + 2);

        const int st = c % 3;
        const uint32_t sA = sbase + st*STB, sB = sA + ABYTES;
        #pragma unroll
        for (int ks = 0; ks < 2; ks++) {
            uint32_t a[4][4];
            #pragma unroll
            for (int mb = 0; mb < 4; mb++) {
                uint32_t addr = sA + (uint32_t)(wm*64 + mb*16 + (lane & 15))*80
                              + (uint32_t)(ks*2 + (lane >> 4))*16;
                ldsm4(a[mb][0], a[mb][1], a[mb][2], a[mb][3], addr);
            }
            uint32_t bb[4][2];
            #pragma unroll
            for (int nb2 = 0; nb2 < 2; nb2++) {
                uint32_t addr = sB + (uint32_t)(wn*32 + nb2*16 + ((lane >> 4) << 3) + (lane & 7))*80
                              + (uint32_t)(ks*2 + ((lane >> 3) & 1))*16;
                uint32_t r0, r1, r2, r3;
                ldsm4(r0, r1, r2, r3, addr);
                bb[2*nb2][0] = r0;   bb[2*nb2][1] = r1;
                bb[2*nb2+1][0] = r2; bb[2*nb2+1][1] = r3;
            }
            #pragma unroll
            for (int mb = 0; mb < 4; mb++)
                #pragma unroll
                for (int nb = 0; nb < 4; nb++)
                    mma16816(acc[mb][nb], a[mb], bb[nb]);
        }
    }

    // ---------------- epilogue ----------------
    #pragma unroll
    for (int mb = 0; mb < 4; mb++) {
        #pragma unroll
        for (int nb = 0; nb < 4; nb++) {
            const float* c4 = acc[mb][nb];
            const int row = bm + wm*64 + mb*16 + (lane >> 2);
            const int col = bn + wn*32 + nb*8 + (lane & 3)*2;
            if (EPI == 0) {
                float b0 = bias ? bias[col]   : 0.f;
                float b1 = bias ? bias[col+1] : 0.f;
                float2 v0 = make_float2(c4[0]*alpha + b0, c4[1]*alpha + b1);
                float2 v1 = make_float2(c4[2]*alpha + b0, c4[3]*alpha + b1);
                *(float2*)(Cz + (size_t)row*ldc + col)     = v0;
                *(float2*)(Cz + (size_t)(row+8)*ldc + col) = v1;
            } else {
                #pragma unroll
                for (int e = 0; e < 4; e++) {
                    int rr = row + (e >> 1)*8, cc = col + (e & 1);
                    size_t off = (size_t)rr*ldc + cc;
                    float v = c4[e] + bias[cc];
                    float g = 1.f / (1.f + expf(-v));
                    Cz[off] = g * e_gcn[off] + (1.f - g) * e_att[off];
                }
            }
        }
    }
}

// ---------------- elementwise split: fp32 -> bf16 hi/lo ----------------
__global__ void split_kernel(const float* __restrict__ src, bf16* __restrict__ hi,
                             bf16* __restrict__ lo, size_t n)
{
    size_t i = (size_t)blockIdx.x*256 + threadIdx.x;
    if (i >= n) return;
    float x = src[i];
    bf16 h = __float2bfloat16(x);
    hi[i] = h;
    lo[i] = __float2bfloat16(x - __bfloat162float(h));
}

// ---------------- weight transpose + split: W[K,N] -> T[N,K] hi/lo ----------------
__global__ void tsplit_kernel(const float* __restrict__ W, bf16* __restrict__ hi,
                              bf16* __restrict__ lo, int K, int N)
{
    __shared__ float tile[32][33];
    int n0 = blockIdx.x*32, k0 = blockIdx.y*32;
    int tx = threadIdx.x, ty = threadIdx.y;
    for (int r = ty; r < 32; r += 8)
        tile[r][tx] = W[(size_t)(k0+r)*N + n0+tx];
    __syncthreads();
    for (int r = ty; r < 32; r += 8) {
        float v = tile[tx][r];
        bf16 h = __float2bfloat16(v);
        size_t o = (size_t)(n0+r)*K + k0+tx;
        hi[o] = h;
        lo[o] = __float2bfloat16(v - __bfloat162float(h));
    }
}

// ---------------- V transpose + split: VT[z][d][j] = QKV[b][j][2D+h*DH+d] ----------------
__global__ void vtsplit_kernel(const float* __restrict__ qkv, bf16* __restrict__ hi,
                               bf16* __restrict__ lo)
{
    __shared__ float tile[32][33];
    int z = blockIdx.z, b = z >> 3, h = z & 7;
    int j0 = blockIdx.x*32, d0 = blockIdx.y*32;
    int tx = threadIdx.x, ty = threadIdx.y;
    const float* src = qkv + (size_t)b*S*3*D + 2*D + h*DH;
    for (int r = ty; r < 32; r += 8)
        tile[r][tx] = src[(size_t)(j0+r)*3*D + d0+tx];
    __syncthreads();
    bf16* Hd = hi + (size_t)z*DH*S;
    bf16* Ld = lo + (size_t)z*DH*S;
    for (int r = ty; r < 32; r += 8) {
        float v = tile[tx][r];
        bf16 hh = __float2bfloat16(v);
        size_t o = (size_t)(d0+r)*S + j0+tx;
        Hd[o] = hh;
        Ld[o] = __float2bfloat16(v - __bfloat162float(hh));
    }
}

// ---------------- concat [GCN | ATT] + split ----------------
__global__ void cat_split_kernel(const float* __restrict__ g, const float* __restrict__ a,
                                 bf16* __restrict__ hi, bf16* __restrict__ lo)
{
    size_t idx = (size_t)blockIdx.x*256 + threadIdx.x;
    size_t row = idx / (2*D);
    int col = (int)(idx - row*(2*D));
    float v = (col < D) ? g[row*D + col] : a[row*D + col - D];
    bf16 h = __float2bfloat16(v);
    hi[idx] = h;
    lo[idx] = __float2bfloat16(v - __bfloat162float(h));
}

// ---------------- softmax over rows of 1024, emits bf16 hi/lo ----------------
__global__ __launch_bounds__(256)
void softmax_kernel(const float* __restrict__ s, bf16* __restrict__ phi, bf16* __restrict__ plo)
{
    const int t = threadIdx.x;
    const size_t ro = (size_t)blockIdx.x * S;
    const float* row = s + ro;
    __shared__ float red[256];
    float v[4];
    float mx = -3.4e38f;
    #pragma unroll
    for (int i = 0; i < 4; i++) { v[i] = row[t + i*256]; mx = fmaxf(mx, v[i]); }
    red[t] = mx; __syncthreads();
    for (int o = 128; o > 0; o >>= 1) { if (t < o) red[t] = fmaxf(red[t], red[t+o]); __syncthreads(); }
    mx = red[0]; __syncthreads();
    float sum = 0.f;
    #pragma unroll
    for (int i = 0; i < 4; i++) { v[i] = expf(v[i] - mx); sum += v[i]; }
    red[t] = sum; __syncthreads();
    for (int o = 128; o > 0; o >>= 1) { if (t < o) red[t] += red[t+o]; __syncthreads(); }
    float inv = 1.f / red[0];
    #pragma unroll
    for (int i = 0; i < 4; i++) {
        float p = v[i] * inv;
        bf16 h = __float2bfloat16(p);
        phi[ro + t + i*256] = h;
        plo[ro + t + i*256] = __float2bfloat16(p - __bfloat162float(h));
    }
}

// ---------------- top-k (k=5) ----------------
__global__ void topk_kernel(const float* __restrict__ sim, int* __restrict__ topk)
{
    int r = blockIdx.x * blockDim.x + threadIdx.x;
    if (r >= BS) return;
    const float* row = sim + (size_t)r * S;
    float tv[KNN]; int ti[KNN];
    #pragma unroll
    for (int p = 0; p < KNN; p++) { tv[p] = -3.4e38f; ti[p] = 0; }
    for (int j = 0; j < S; j++) {
        float v = row[j];
        if (v > tv[KNN-1]) {
            int p = KNN - 1;
            while (p > 0 && v > tv[p-1]) { tv[p] = tv[p-1]; ti[p] = ti[p-1]; p--; }
            tv[p] = v; ti[p] = j;
        }
    }
    #pragma unroll
    for (int p = 0; p < KNN; p++) topk[r*KNN + p] = ti[p];
}

__global__ void scatter_kernel(const int* __restrict__ topk, unsigned* __restrict__ adj)
{
    int r = blockIdx.x * blockDim.x + threadIdx.x;
    if (r >= BS) return;
    int b = r >> 10, i = r & 1023;
    unsigned* base = adj + (size_t)b * S * 32;
    atomicOr(&base[i*32 + (i >> 5)], 1u << (i & 31));
    #pragma unroll
    for (int p = 0; p < KNN; p++) {
        int j = topk[r*KNN + p];
        atomicOr(&base[i*32 + (j >> 5)], 1u << (j & 31));
        atomicOr(&base[j*32 + (i >> 5)], 1u << (i & 31));
    }
}

__global__ void deg_kernel(const unsigned* __restrict__ adj, float* __restrict__ dinv)
{
    int r = blockIdx.x * blockDim.x + threadIdx.x;
    if (r >= BS) return;
    int cnt = 0;
    #pragma unroll
    for (int w = 0; w < 32; w++) cnt += __popc(adj[r*32 + w]);
    dinv[r] = rsqrtf((float)cnt);
}

// ---------------- sparse GCN aggregation ----------------
__global__ __launch_bounds__(256)
void gcn_agg(const float* __restrict__ xg, const unsigned* __restrict__ adj,
             const float* __restrict__ dinv, const float* __restrict__ bias,
             float* __restrict__ out)
{
    const int r = blockIdx.x;
    const int t = threadIdx.x;
    const int b = r >> 10;
    const float di = dinv[r];
    float a0 = 0.f, a1 = 0.f, a2 = 0.f;
    for (int w = 0; w < 32; w++) {
        unsigned m = adj[r*32 + w];
        while (m) {
            int bit = __ffs(m) - 1; m &= m - 1;
            int j = (b << 10) + (w << 5) + bit;
            float c = di * dinv[j];
            const float* xr = xg + (size_t)j * D;
            a0 += c * xr[t]; a1 += c * xr[t + 256]; a2 += c * xr[t + 512];
        }
    }
    float* o = out + (size_t)r * D;
    o[t]       = a0 + bias[t];
    o[t + 256] = a1 + bias[t + 256];
    o[t + 512] = a2 + bias[t + 512];
}

// ---------------- LayerNorm(fused + h) -> h (+ bf16 split) ----------------
__global__ __launch_bounds__(256)
void ln_kernel(const float* __restrict__ fused, float* __restrict__ h,
               bf16* __restrict__ hhi, bf16* __restrict__ hlo,
               const float* __restrict__ scale, const float* __restrict__ bias)
{
    const int r = blockIdx.x, t = threadIdx.x;
    __shared__ float red[256];
    const size_t base = (size_t)r * D;
    float v0 = fused[base + t]       + h[base + t];
    float v1 = fused[base + t + 256] + h[base + t + 256];
    float v2 = fused[base + t + 512] + h[base + t + 512];
    red[t] = v0 + v1 + v2; __syncthreads();
    for (int o = 128; o > 0; o >>= 1) { if (t < o) red[t] += red[t+o]; __syncthreads(); }
    float mu = red[0] * (1.f / D); __syncthreads();
    float d0 = v0 - mu, d1 = v1 - mu, d2 = v2 - mu;
    red[t] = d0*d0 + d1*d1 + d2*d2; __syncthreads();
    for (int o = 128; o > 0; o >>= 1) { if (t < o) red[t] += red[t+o]; __syncthreads(); }
    float rs = rsqrtf(red[0] * (1.f / D) + 1e-5f);
    float o0 = d0 * rs * scale[t]       + bias[t];
    float o1 = d1 * rs * scale[t + 256] + bias[t + 256];
    float o2 = d2 * rs * scale[t + 512] + bias[t + 512];
    h[base + t] = o0; h[base + t + 256] = o1; h[base + t + 512] = o2;
    bf16 h0 = __float2bfloat16(o0), h1 = __float2bfloat16(o1), h2 = __float2bfloat16(o2);
    hhi[base + t] = h0; hhi[base + t + 256] = h1; hhi[base + t + 512] = h2;
    hlo[base + t]       = __float2bfloat16(o0 - __bfloat162float(h0));
    hlo[base + t + 256] = __float2bfloat16(o1 - __bfloat162float(h1));
    hlo[base + t + 512] = __float2bfloat16(o2 - __bfloat162float(h2));
}

// =====================================================================
extern "C" void kernel_launch(void* const* d_in, const int* in_sizes, int n_in,
                              void* d_out, int out_size)
{
    const float* x      = (const float*)d_in[0];
    const float* gcn_w  = (const float*)d_in[1];
    const float* gcn_b  = (const float*)d_in[2];
    const float* ain_w  = (const float*)d_in[3];
    const float* ain_b  = (const float*)d_in[4];
    const float* aout_w = (const float*)d_in[5];
    const float* aout_b = (const float*)d_in[6];
    const float* gate_w = (const float*)d_in[7];
    const float* gate_b = (const float*)d_in[8];
    const float* ln_s   = (const float*)d_in[9];
    const float* ln_b   = (const float*)d_in[10];
    const float* proj_w = (const float*)d_in[11];
    const float* proj_b = (const float*)d_in[12];
    float* out = (float*)d_out;

    float *Sb, *H, *XG, *GCN, *QKV, *O, *ATT, *FUSED, *DINV;
    bf16 *Phi, *Plo, *Hhi, *Hlo, *QKVhi, *QKVlo, *Ohi, *Olo, *CAThi, *CATlo, *VThi, *VTlo;
    bf16 *WGhi, *WGlo, *WAIhi, *WAIlo, *WAOhi, *WAOlo, *WGThi, *WGTlo, *WPhi, *WPlo;
    unsigned* ADJ; int* TOPK;
    cudaGetSymbolAddress((void**)&Sb, g_S);       cudaGetSymbolAddress((void**)&H, g_H);
    cudaGetSymbolAddress((void**)&XG, g_XG);      cudaGetSymbolAddress((void**)&GCN, g_GCN);
    cudaGetSymbolAddress((void**)&QKV, g_QKV);    cudaGetSymbolAddress((void**)&O, g_O);
    cudaGetSymbolAddress((void**)&ATT, g_ATT);    cudaGetSymbolAddress((void**)&FUSED, g_FUSED);
    cudaGetSymbolAddress((void**)&DINV, g_dinv);  cudaGetSymbolAddress((void**)&ADJ, g_adj);
    cudaGetSymbolAddress((void**)&TOPK, g_topk);
    cudaGetSymbolAddress((void**)&Phi, g_Phi);    cudaGetSymbolAddress((void**)&Plo, g_Plo);
    cudaGetSymbolAddress((void**)&Hhi, g_Hhi);    cudaGetSymbolAddress((void**)&Hlo, g_Hlo);
    cudaGetSymbolAddress((void**)&QKVhi, g_QKVhi); cudaGetSymbolAddress((void**)&QKVlo, g_QKVlo);
    cudaGetSymbolAddress((void**)&Ohi, g_Ohi);    cudaGetSymbolAddress((void**)&Olo, g_Olo);
    cudaGetSymbolAddress((void**)&CAThi, g_CAThi); cudaGetSymbolAddress((void**)&CATlo, g_CATlo);
    cudaGetSymbolAddress((void**)&VThi, g_VThi);  cudaGetSymbolAddress((void**)&VTlo, g_VTlo);
    cudaGetSymbolAddress((void**)&WGhi, g_WGhi);  cudaGetSymbolAddress((void**)&WGlo, g_WGlo);
    cudaGetSymbolAddress((void**)&WAIhi, g_WAIhi); cudaGetSymbolAddress((void**)&WAIlo, g_WAIlo);
    cudaGetSymbolAddress((void**)&WAOhi, g_WAOhi); cudaGetSymbolAddress((void**)&WAOlo, g_WAOlo);
    cudaGetSymbolAddress((void**)&WGThi, g_WGThi); cudaGetSymbolAddress((void**)&WGTlo, g_WGTlo);
    cudaGetSymbolAddress((void**)&WPhi, g_WPhi);  cudaGetSymbolAddress((void**)&WPlo, g_WPlo);

    // dynamic smem: 3 stages * (A 128*80 + B BN*80)
    const int SM128 = 3 * (128*80 + 128*80);   // 61440
    const int SM96  = 3 * (128*80 +  96*80);   // 53760
    cudaFuncSetAttribute((const void*)hmma_gemm<128,4,0>, cudaFuncAttributeMaxDynamicSharedMemorySize, SM128);
    cudaFuncSetAttribute((const void*)hmma_gemm<128,4,1>, cudaFuncAttributeMaxDynamicSharedMemorySize, SM128);
    cudaFuncSetAttribute((const void*)hmma_gemm<96,3,0>,  cudaFuncAttributeMaxDynamicSharedMemorySize, SM96);

    cudaMemsetAsync(ADJ, 0, (size_t)BS*32*sizeof(unsigned), 0);
    cudaMemcpyAsync(H, x, (size_t)BS*D*sizeof(float), cudaMemcpyDeviceToDevice, 0);
    split_kernel<<<BS*D/256, 256>>>(x, Hhi, Hlo, (size_t)BS*D);

    // --- graph construction: sim = x x^T per batch (fp32 SIMT — exact for top-k) ---
    dot_kernel<<<dim3(8, 8, B), 256>>>(x, Sb, D);
    topk_kernel<<<BS/256, 256>>>(Sb, TOPK);
    scatter_kernel<<<BS/256, 256>>>(TOPK, ADJ);
    deg_kernel<<<BS/256, 256>>>(ADJ, DINV);

    const float att_scale = 1.0f / sqrtf((float)DH);
    dim3 tb(32, 8);

    for (int l = 0; l < L_LAYERS; l++) {
        const float* gw  = gcn_w  + (size_t)l*D*D;
        const float* gb  = gcn_b  + (size_t)l*D;
        const float* aiw = ain_w  + (size_t)l*D*3*D;
        const float* aib = ain_b  + (size_t)l*3*D;
        const float* aow = aout_w + (size_t)l*D*D;
        const float* aob = aout_b + (size_t)l*D;
        const float* gtw = gate_w + (size_t)l*2*D*D;
        const float* gtb = gate_b + (size_t)l*D;

        // transpose+split this layer's weights -> [N,K] bf16 hi/lo
        tsplit_kernel<<<dim3(D/32, D/32), tb>>>(gw, WGhi, WGlo, D, D);
        tsplit_kernel<<<dim3(3*D/32, D/32), tb>>>(aiw, WAIhi, WAIlo, D, 3*D);
        tsplit_kernel<<<dim3(D/32, D/32), tb>>>(aow, WAOhi, WAOlo, D, D);
        tsplit_kernel<<<dim3(D/32, 2*D/32), tb>>>(gtw, WGThi, WGTlo, 2*D, D);

        // GCN branch: XG = H @ gcn_w, then sparse aggregation (+bias)
        hmma_gemm<128,4,0><<<dim3(D/128, BS/128, 1), 256, SM128>>>(
            Hhi, Hlo, WGhi, WGlo, XG, D, D, D, D,
            0,0,0,0,0,0, 1, 1.0f, nullptr, nullptr, nullptr);
        gcn_agg<<<BS, 256>>>(XG, ADJ, DINV, gb, GCN);

        // Attention branch
        hmma_gemm<128,4,0><<<dim3(3*D/128, BS/128, 1), 256, SM128>>>(
            Hhi, Hlo, WAIhi, WAIlo, QKV, D, D, D, 3*D,
            0,0,0,0,0,0, 1, 1.0f, aib, nullptr, nullptr);
        split_kernel<<<(int)((size_t)BS*3*D/256), 256>>>(QKV, QKVhi, QKVlo, (size_t)BS*3*D);
        vtsplit_kernel<<<dim3(S/32, DH/32, ZN), tb>>>(QKV, VThi, VTlo);

        // scores = (Q K^T) * scale   [z = b*8+h]
        hmma_gemm<128,4,0><<<dim3(8, 8, ZN), 256, SM128>>>(
            QKVhi, QKVlo, QKVhi + D, QKVlo + D, Sb, DH, 3*D, 3*D, S,
            (long long)S*3*D, DH, (long long)S*3*D, DH,
            (long long)HEADS*S*S, (long long)S*S, HEADS,
            att_scale, nullptr, nullptr, nullptr);
        softmax_kernel<<<ZN*S, 256>>>(Sb, Phi, Plo);

        // O = P @ V  (VT is [z][96][1024] K-major)
        hmma_gemm<96,3,0><<<dim3(1, 8, ZN), 192, SM96>>>(
            Phi, Plo, VThi, VTlo, O, S, S, S, D,
            (long long)HEADS*S*S, (long long)S*S,
            (long long)HEADS*DH*S, (long long)DH*S,
            (long long)S*D, DH, HEADS,
            1.0f, nullptr, nullptr, nullptr);
        split_kernel<<<BS*D/256, 256>>>(O, Ohi, Olo, (size_t)BS*D);

        // attn out-proj
        hmma_gemm<128,4,0><<<dim3(D/128, BS/128, 1), 256, SM128>>>(
            Ohi, Olo, WAOhi, WAOlo, ATT, D, D, D, D,
            0,0,0,0,0,0, 1, 1.0f, aob, nullptr, nullptr);

        // gate + fuse (fused sigmoid epilogue), then LN residual (+ split)
        cat_split_kernel<<<(int)((size_t)BS*2*D/256), 256>>>(GCN, ATT, CAThi, CATlo);
        hmma_gemm<128,4,1><<<dim3(D/128, BS/128, 1), 256, SM128>>>(
            CAThi, CATlo, WGThi, WGTlo, FUSED, 2*D, 2*D, 2*D, D,
            0,0,0,0,0,0, 1, 1.0f, gtb, GCN, ATT);
        ln_kernel<<<BS, 256>>>(FUSED, H, Hhi, Hlo, ln_s + (size_t)l*D, ln_b + (size_t)l*D);
    }

    // final projection -> d_out
    tsplit_kernel<<<dim3(D/32, D/32), tb>>>(proj_w, WPhi, WPlo, D, D);
    hmma_gemm<128,4,0><<<dim3(D/128, BS/128, 1), 256, SM128>>>(
        Hhi, Hlo, WPhi, WPlo, out, D, D, D, D,
        0,0,0,0,0,0, 1, 1.0f, proj_b, nullptr, nullptr);
}

// round 13
// speedup vs baseline: 1.7555x; 1.0228x over previous
#include <cuda_runtime.h>
#include <cuda_bf16.h>
#include <math.h>
#include <stdint.h>

#define B 8
#define S 1024
#define D 768
#define BS (B*S)          // 8192
#define HEADS 8
#define DH 96
#define L_LAYERS 3
#define KNN 5
#define ZN (B*HEADS)      // 64

typedef __nv_bfloat16 bf16;

// ---------------- scratch (static device globals; no runtime alloc) ----------------
__device__ float g_S[(size_t)HEADS*S*S];              // 32MB rotating: sim (all batches) / per-batch scores
__device__ bf16  g_Phi[(size_t)ZN*S*S];
__device__ bf16  g_Plo[(size_t)ZN*S*S];
__device__ float g_H[BS*D];
__device__ float g_XG[BS*D];
__device__ float g_GCN[BS*D];
__device__ float g_ATT[BS*D];
__device__ float g_FUSED[BS*D];
__device__ bf16  g_Hhi[BS*D],  g_Hlo[BS*D];
__device__ bf16  g_QKVhi[(size_t)BS*3*D], g_QKVlo[(size_t)BS*3*D];
__device__ bf16  g_Ohi[BS*D],  g_Olo[BS*D];
__device__ bf16  g_CAThi[(size_t)BS*2*D], g_CATlo[(size_t)BS*2*D];
__device__ bf16  g_VThi[(size_t)ZN*DH*S], g_VTlo[(size_t)ZN*DH*S];
__device__ bf16  g_WGhi[D*D],      g_WGlo[D*D];
__device__ bf16  g_WAIhi[3*D*D],   g_WAIlo[3*D*D];
__device__ bf16  g_WAOhi[D*D],     g_WAOlo[D*D];
__device__ bf16  g_WGThi[2*D*D],   g_WGTlo[2*D*D];
__device__ bf16  g_WPhi[D*D],      g_WPlo[D*D];
__device__ unsigned g_adj[BS*32];
__device__ float g_dinv[BS];
__device__ int   g_topk[BS*KNN];

// ====================== helpers (baseline PTX only: cp.async / ldmatrix / mma.sync) ======================
__device__ __forceinline__ uint32_t smem_u32(const void* p) {
    uint32_t a;
    asm("{ .reg .u64 t; cvta.to.shared.u64 t, %1; cvt.u32.u64 %0, t; }" : "=r"(a) : "l"(p));
    return a;
}
__device__ __forceinline__ void cpasync16(uint32_t sdst, const void* gsrc) {
    asm volatile("cp.async.cg.shared.global [%0], [%1], 16;" :: "r"(sdst), "l"(gsrc) : "memory");
}
__device__ __forceinline__ void ldsm4(uint32_t& r0, uint32_t& r1, uint32_t& r2, uint32_t& r3, uint32_t addr) {
    asm volatile("ldmatrix.sync.aligned.m8n8.x4.shared.b16 {%0,%1,%2,%3}, [%4];"
                 : "=r"(r0), "=r"(r1), "=r"(r2), "=r"(r3) : "r"(addr));
}
__device__ __forceinline__ void mma16816(float* c, const uint32_t* a, const uint32_t* b) {
    asm volatile("mma.sync.aligned.m16n8k16.row.col.f32.bf16.bf16.f32 "
                 "{%0,%1,%2,%3}, {%4,%5,%6,%7}, {%8,%9}, {%0,%1,%2,%3};"
                 : "+f"(c[0]), "+f"(c[1]), "+f"(c[2]), "+f"(c[3])
                 : "r"(a[0]), "r"(a[1]), "r"(a[2]), "r"(a[3]), "r"(b[0]), "r"(b[1]));
}

// =====================================================================
// fp32 SIMT dot kernel for sim (graph needs fp32-exact values for top-k)
// =====================================================================
__global__ __launch_bounds__(256)
void dot_kernel(const float* __restrict__ Ab, float* __restrict__ Cb, int K)
{
    const int z = blockIdx.z;
    const float* A = Ab + (size_t)z * S * K;
    float* C = Cb + (size_t)z * S * S;
    const int bm = blockIdx.y * 128, bn = blockIdx.x * 128;
    const int t = threadIdx.x;
    const int tx = t & 15, ty = t >> 4;
    __shared__ float As[16][132];
    __shared__ float Bs[16][132];
    float acc[8][8];
    #pragma unroll
    for (int i = 0; i < 8; i++)
        #pragma unroll
        for (int j = 0; j < 8; j++) acc[i][j] = 0.f;

    for (int k0 = 0; k0 < K; k0 += 16) {
        #pragma unroll
        for (int i = 0; i < 2; i++) {
            int f4 = t + i*256;
            int row = f4 >> 2, kc = (f4 & 3) * 4;
            float4 v = *(const float4*)(A + (size_t)(bm + row)*K + k0 + kc);
            As[kc+0][row] = v.x; As[kc+1][row] = v.y;
            As[kc+2][row] = v.z; As[kc+3][row] = v.w;
            float4 w = *(const float4*)(A + (size_t)(bn + row)*K + k0 + kc);
            Bs[kc+0][row] = w.x; Bs[kc+1][row] = w.y;
            Bs[kc+2][row] = w.z; Bs[kc+3][row] = w.w;
        }
        __syncthreads();
        #pragma unroll
        for (int kk = 0; kk < 16; kk++) {
            float a[8], b[8];
            #pragma unroll
            for (int i = 0; i < 8; i++) a[i] = As[kk][ty*8 + i];
            #pragma unroll
            for (int j = 0; j < 8; j++) b[j] = Bs[kk][tx*8 + j];
            #pragma unroll
            for (int i = 0; i < 8; i++)
                #pragma unroll
                for (int j = 0; j < 8; j++)
                    acc[i][j] += a[i] * b[j];
        }
        __syncthreads();
    }
    #pragma unroll
    for (int i = 0; i < 8; i++)
        #pragma unroll
        for (int j = 0; j < 8; j++)
            C[(size_t)(bm + ty*8 + i) * S + bn + tx*8 + j] = acc[i][j];
}

// =====================================================================
// Split-bf16 HMMA GEMM: acc[z][m][n] = sum_k A[m,k]*B[n,k] (3 passes)
// EPI 0: C = acc*alpha (+bias) fp32.  EPI 1: sigmoid gate fuse (fp32).
// EPI 2: split output -> hi_out/lo_out bf16 pairs (+bias, *alpha).
// =====================================================================
template<int BN, int WN, int EPI>
__global__ void __launch_bounds__(256)
hmma_gemm(const bf16* __restrict__ Ahi, const bf16* __restrict__ Alo,
          const bf16* __restrict__ Bhi, const bf16* __restrict__ Blo,
          float* __restrict__ C, int K, int lda, int ldb, int ldc,
          long long aZb, long long aZh, long long bZb, long long bZh,
          long long cZb, long long cZh, int HZ,
          float alpha, const float* __restrict__ bias,
          const float* __restrict__ e_gcn, const float* __restrict__ e_att,
          bf16* __restrict__ hi_out, bf16* __restrict__ lo_out)
{
    extern __shared__ char smem[];
    constexpr int NTH = 64 * WN;
    constexpr int ABYTES = 128 * 80;
    constexpr int BBYTES = BN * 80;
    constexpr int STB = ABYTES + BBYTES;
    const uint32_t sbase = smem_u32(smem);
    const int t = threadIdx.x, lane = t & 31, wid = t >> 5;
    const int wm = wid / WN, wn = wid % WN;

    const int z = blockIdx.z;
    const int zb = z / HZ, zh = z - zb * HZ;
    const bf16* Ah = Ahi + zb*aZb + zh*aZh;
    const bf16* Al = Alo + zb*aZb + zh*aZh;
    const bf16* Bh = Bhi + zb*bZb + zh*bZh;
    const bf16* Bl = Blo + zb*bZb + zh*bZh;
    const size_t zoff = (size_t)(zb*cZb + zh*cZh);
    const int bm = blockIdx.y * 128, bn = blockIdx.x * BN;

    const int CPP = K >> 5;
    const int NC = 3 * CPP;

    auto issue = [&](int c) {
        const int p = c / CPP, kk = c - p*CPP;
        const bf16* Ap = (p == 2) ? Al : Ah;
        const bf16* Bp = (p == 1) ? Bl : Bh;
        const int st = c % 3, k0 = kk * 32;
        const uint32_t sA = sbase + st*STB, sB = sA + ABYTES;
        for (int i = t; i < 512; i += NTH) {
            int row = i >> 2, ch = i & 3;
            cpasync16(sA + row*80 + ch*16, Ap + (size_t)(bm + row)*lda + k0 + ch*8);
        }
        for (int i = t; i < BN*4; i += NTH) {
            int row = i >> 2, ch = i & 3;
            cpasync16(sB + row*80 + ch*16, Bp + (size_t)(bn + row)*ldb + k0 + ch*8);
        }
        asm volatile("cp.async.commit_group;" ::: "memory");
    };

    float acc[4][4][4];
    #pragma unroll
    for (int i = 0; i < 4; i++)
        #pragma unroll
        for (int j = 0; j < 4; j++)
            #pragma unroll
            for (int e = 0; e < 4; e++) acc[i][j][e] = 0.f;

    issue(0);
    if (NC > 1) issue(1);

    for (int c = 0; c < NC; c++) {
        if (c + 1 < NC) asm volatile("cp.async.wait_group 1;" ::: "memory");
        else            asm volatile("cp.async.wait_group 0;" ::: "memory");
        __syncthreads();
        if (c + 2 < NC) issue(c + 2);

        const int st = c % 3;
        const uint32_t sA = sbase + st*STB, sB = sA + ABYTES;
        #pragma unroll
        for (int ks = 0; ks < 2; ks++) {
            uint32_t a[4][4];
            #pragma unroll
            for (int mb = 0; mb < 4; mb++) {
                uint32_t addr = sA + (uint32_t)(wm*64 + mb*16 + (lane & 15))*80
                              + (uint32_t)(ks*2 + (lane >> 4))*16;
                ldsm4(a[mb][0], a[mb][1], a[mb][2], a[mb][3], addr);
            }
            uint32_t bb[4][2];
            #pragma unroll
            for (int nb2 = 0; nb2 < 2; nb2++) {
                uint32_t addr = sB + (uint32_t)(wn*32 + nb2*16 + ((lane >> 4) << 3) + (lane & 7))*80
                              + (uint32_t)(ks*2 + ((lane >> 3) & 1))*16;
                uint32_t r0, r1, r2, r3;
                ldsm4(r0, r1, r2, r3, addr);
                bb[2*nb2][0] = r0;   bb[2*nb2][1] = r1;
                bb[2*nb2+1][0] = r2; bb[2*nb2+1][1] = r3;
            }
            #pragma unroll
            for (int mb = 0; mb < 4; mb++)
                #pragma unroll
                for (int nb = 0; nb < 4; nb++)
                    mma16816(acc[mb][nb], a[mb], bb[nb]);
        }
    }

    // ---------------- epilogue ----------------
    #pragma unroll
    for (int mb = 0; mb < 4; mb++) {
        #pragma unroll
        for (int nb = 0; nb < 4; nb++) {
            const float* c4 = acc[mb][nb];
            const int row = bm + wm*64 + mb*16 + (lane >> 2);
            const int col = bn + wn*32 + nb*8 + (lane & 3)*2;
            if (EPI == 0) {
                float* Cz = C + zoff;
                float b0 = bias ? bias[col]   : 0.f;
                float b1 = bias ? bias[col+1] : 0.f;
                float2 v0 = make_float2(c4[0]*alpha + b0, c4[1]*alpha + b1);
                float2 v1 = make_float2(c4[2]*alpha + b0, c4[3]*alpha + b1);
                *(float2*)(Cz + (size_t)row*ldc + col)     = v0;
                *(float2*)(Cz + (size_t)(row+8)*ldc + col) = v1;
            } else if (EPI == 1) {
                float* Cz = C + zoff;
                #pragma unroll
                for (int e = 0; e < 4; e++) {
                    int rr = row + (e >> 1)*8, cc = col + (e & 1);
                    size_t off = (size_t)rr*ldc + cc;
                    float v = c4[e] + bias[cc];
                    float g = 1.f / (1.f + expf(-v));
                    Cz[off] = g * e_gcn[off] + (1.f - g) * e_att[off];
                }
            } else {
                bf16* hiP = hi_out + zoff;
                bf16* loP = lo_out + zoff;
                float b0 = bias ? bias[col]   : 0.f;
                float b1 = bias ? bias[col+1] : 0.f;
                #pragma unroll
                for (int rr2 = 0; rr2 < 2; rr2++) {
                    float vx = c4[rr2*2+0]*alpha + b0;
                    float vy = c4[rr2*2+1]*alpha + b1;
                    __nv_bfloat162 hp = __floats2bfloat162_rn(vx, vy);
                    __nv_bfloat162 lp = __floats2bfloat162_rn(
                        vx - __bfloat162float(hp.x), vy - __bfloat162float(hp.y));
                    size_t off = (size_t)(row + rr2*8)*ldc + col;
                    *(__nv_bfloat162*)(hiP + off) = hp;
                    *(__nv_bfloat162*)(loP + off) = lp;
                }
            }
        }
    }
}

// ---------------- elementwise split: fp32 -> bf16 hi/lo ----------------
__global__ void split_kernel(const float* __restrict__ src, bf16* __restrict__ hi,
                             bf16* __restrict__ lo, size_t n)
{
    size_t i = (size_t)blockIdx.x*256 + threadIdx.x;
    if (i >= n) return;
    float x = src[i];
    bf16 h = __float2bfloat16(x);
    hi[i] = h;
    lo[i] = __float2bfloat16(x - __bfloat162float(h));
}

// ---------------- weight transpose + split: W[K,N] -> T[N,K] hi/lo ----------------
__global__ void tsplit_kernel(const float* __restrict__ W, bf16* __restrict__ hi,
                              bf16* __restrict__ lo, int K, int N)
{
    __shared__ float tile[32][33];
    int n0 = blockIdx.x*32, k0 = blockIdx.y*32;
    int tx = threadIdx.x, ty = threadIdx.y;
    for (int r = ty; r < 32; r += 8)
        tile[r][tx] = W[(size_t)(k0+r)*N + n0+tx];
    __syncthreads();
    for (int r = ty; r < 32; r += 8) {
        float v = tile[tx][r];
        bf16 h = __float2bfloat16(v);
        size_t o = (size_t)(n0+r)*K + k0+tx;
        hi[o] = h;
        lo[o] = __float2bfloat16(v - __bfloat162float(h));
    }
}

// ---------------- V transpose + split from QKV hi/lo pairs ----------------
__global__ void vtsplit_kernel(const bf16* __restrict__ qhi, const bf16* __restrict__ qlo,
                               bf16* __restrict__ hi, bf16* __restrict__ lo)
{
    __shared__ float tile[32][33];
    int z = blockIdx.z, b = z >> 3, h = z & 7;
    int j0 = blockIdx.x*32, d0 = blockIdx.y*32;
    int tx = threadIdx.x, ty = threadIdx.y;
    const size_t base = (size_t)b*S*3*D + 2*D + h*DH;
    for (int r = ty; r < 32; r += 8) {
        size_t o = base + (size_t)(j0+r)*3*D + d0+tx;
        tile[r][tx] = __bfloat162float(qhi[o]) + __bfloat162float(qlo[o]);
    }
    __syncthreads();
    bf16* Hd = hi + (size_t)z*DH*S;
    bf16* Ld = lo + (size_t)z*DH*S;
    for (int r = ty; r < 32; r += 8) {
        float v = tile[tx][r];
        bf16 hh = __float2bfloat16(v);
        size_t o = (size_t)(d0+r)*S + j0+tx;
        Hd[o] = hh;
        Ld[o] = __float2bfloat16(v - __bfloat162float(hh));
    }
}

// ---------------- concat [GCN | ATT] + split ----------------
__global__ void cat_split_kernel(const float* __restrict__ g, const float* __restrict__ a,
                                 bf16* __restrict__ hi, bf16* __restrict__ lo)
{
    size_t idx = (size_t)blockIdx.x*256 + threadIdx.x;
    size_t row = idx / (2*D);
    int col = (int)(idx - row*(2*D));
    float v = (col < D) ? g[row*D + col] : a[row*D + col - D];
    bf16 h = __float2bfloat16(v);
    hi[idx] = h;
    lo[idx] = __float2bfloat16(v - __bfloat162float(h));
}

// ---------------- softmax over rows of 1024, emits bf16 hi/lo ----------------
__global__ __launch_bounds__(256)
void softmax_kernel(const float* __restrict__ s, bf16* __restrict__ phi, bf16* __restrict__ plo)
{
    const int t = threadIdx.x;
    const size_t ro = (size_t)blockIdx.x * S;
    const float* row = s + ro;
    __shared__ float red[256];
    float v[4];
    float mx = -3.4e38f;
    #pragma unroll
    for (int i = 0; i < 4; i++) { v[i] = row[t + i*256]; mx = fmaxf(mx, v[i]); }
    red[t] = mx; __syncthreads();
    for (int o = 128; o > 0; o >>= 1) { if (t < o) red[t] = fmaxf(red[t], red[t+o]); __syncthreads(); }
    mx = red[0]; __syncthreads();
    float sum = 0.f;
    #pragma unroll
    for (int i = 0; i < 4; i++) { v[i] = expf(v[i] - mx); sum += v[i]; }
    red[t] = sum; __syncthreads();
    for (int o = 128; o > 0; o >>= 1) { if (t < o) red[t] += red[t+o]; __syncthreads(); }
    float inv = 1.f / red[0];
    #pragma unroll
    for (int i = 0; i < 4; i++) {
        float p = v[i] * inv;
        bf16 h = __float2bfloat16(p);
        phi[ro + t + i*256] = h;
        plo[ro + t + i*256] = __float2bfloat16(p - __bfloat162float(h));
    }
}

// ---------------- top-k (k=5) ----------------
__global__ void topk_kernel(const float* __restrict__ sim, int* __restrict__ topk)
{
    int r = blockIdx.x * blockDim.x + threadIdx.x;
    if (r >= BS) return;
    const float* row = sim + (size_t)r * S;
    float tv[KNN]; int ti[KNN];
    #pragma unroll
    for (int p = 0; p < KNN; p++) { tv[p] = -3.4e38f; ti[p] = 0; }
    for (int j = 0; j < S; j++) {
        float v = row[j];
        if (v > tv[KNN-1]) {
            int p = KNN - 1;
            while (p > 0 && v > tv[p-1]) { tv[p] = tv[p-1]; ti[p] = ti[p-1]; p--; }
            tv[p] = v; ti[p] = j;
        }
    }
    #pragma unroll
    for (int p = 0; p < KNN; p++) topk[r*KNN + p] = ti[p];
}

__global__ void scatter_kernel(const int* __restrict__ topk, unsigned* __restrict__ adj)
{
    int r = blockIdx.x * blockDim.x + threadIdx.x;
    if (r >= BS) return;
    int b = r >> 10, i = r & 1023;
    unsigned* base = adj + (size_t)b * S * 32;
    atomicOr(&base[i*32 + (i >> 5)], 1u << (i & 31));
    #pragma unroll
    for (int p = 0; p < KNN; p++) {
        int j = topk[r*KNN + p];
        atomicOr(&base[i*32 + (j >> 5)], 1u << (j & 31));
        atomicOr(&base[j*32 + (i >> 5)], 1u << (i & 31));
    }
}

__global__ void deg_kernel(const unsigned* __restrict__ adj, float* __restrict__ dinv)
{
    int r = blockIdx.x * blockDim.x + threadIdx.x;
    if (r >= BS) return;
    int cnt = 0;
    #pragma unroll
    for (int w = 0; w < 32; w++) cnt += __popc(adj[r*32 + w]);
    dinv[r] = rsqrtf((float)cnt);
}

// ---------------- sparse GCN aggregation ----------------
__global__ __launch_bounds__(256)
void gcn_agg(const float* __restrict__ xg, const unsigned* __restrict__ adj,
             const float* __restrict__ dinv, const float* __restrict__ bias,
             float* __restrict__ out)
{
    const int r = blockIdx.x;
    const int t = threadIdx.x;
    const int b = r >> 10;
    const float di = dinv[r];
    float a0 = 0.f, a1 = 0.f, a2 = 0.f;
    for (int w = 0; w < 32; w++) {
        unsigned m = adj[r*32 + w];
        while (m) {
            int bit = __ffs(m) - 1; m &= m - 1;
            int j = (b << 10) + (w << 5) + bit;
            float c = di * dinv[j];
            const float* xr = xg + (size_t)j * D;
            a0 += c * xr[t]; a1 += c * xr[t + 256]; a2 += c * xr[t + 512];
        }
    }
    float* o = out + (size_t)r * D;
    o[t]       = a0 + bias[t];
    o[t + 256] = a1 + bias[t + 256];
    o[t + 512] = a2 + bias[t + 512];
}

// ---------------- LayerNorm(fused + h) -> h (+ bf16 split) ----------------
__global__ __launch_bounds__(256)
void ln_kernel(const float* __restrict__ fused, float* __restrict__ h,
               bf16* __restrict__ hhi, bf16* __restrict__ hlo,
               const float* __restrict__ scale, const float* __restrict__ bias)
{
    const int r = blockIdx.x, t = threadIdx.x;
    __shared__ float red[256];
    const size_t base = (size_t)r * D;
    float v0 = fused[base + t]       + h[base + t];
    float v1 = fused[base + t + 256] + h[base + t + 256];
    float v2 = fused[base + t + 512] + h[base + t + 512];
    red[t] = v0 + v1 + v2; __syncthreads();
    for (int o = 128; o > 0; o >>= 1) { if (t < o) red[t] += red[t+o]; __syncthreads(); }
    float mu = red[0] * (1.f / D); __syncthreads();
    float d0 = v0 - mu, d1 = v1 - mu, d2 = v2 - mu;
    red[t] = d0*d0 + d1*d1 + d2*d2; __syncthreads();
    for (int o = 128; o > 0; o >>= 1) { if (t < o) red[t] += red[t+o]; __syncthreads(); }
    float rs = rsqrtf(red[0] * (1.f / D) + 1e-5f);
    float o0 = d0 * rs * scale[t]       + bias[t];
    float o1 = d1 * rs * scale[t + 256] + bias[t + 256];
    float o2 = d2 * rs * scale[t + 512] + bias[t + 512];
    h[base + t] = o0; h[base + t + 256] = o1; h[base + t + 512] = o2;
    bf16 h0 = __float2bfloat16(o0), h1 = __float2bfloat16(o1), h2 = __float2bfloat16(o2);
    hhi[base + t] = h0; hhi[base + t + 256] = h1; hhi[base + t + 512] = h2;
    hlo[base + t]       = __float2bfloat16(o0 - __bfloat162float(h0));
    hlo[base + t + 256] = __float2bfloat16(o1 - __bfloat162float(h1));
    hlo[base + t + 512] = __float2bfloat16(o2 - __bfloat162float(h2));
}

// =====================================================================
extern "C" void kernel_launch(void* const* d_in, const int* in_sizes, int n_in,
                              void* d_out, int out_size)
{
    const float* x      = (const float*)d_in[0];
    const float* gcn_w  = (const float*)d_in[1];
    const float* gcn_b  = (const float*)d_in[2];
    const float* ain_w  = (const float*)d_in[3];
    const float* ain_b  = (const float*)d_in[4];
    const float* aout_w = (const float*)d_in[5];
    const float* aout_b = (const float*)d_in[6];
    const float* gate_w = (const float*)d_in[7];
    const float* gate_b = (const float*)d_in[8];
    const float* ln_s   = (const float*)d_in[9];
    const float* ln_b   = (const float*)d_in[10];
    const float* proj_w = (const float*)d_in[11];
    const float* proj_b = (const float*)d_in[12];
    float* out = (float*)d_out;

    float *Sb, *H, *XG, *GCN, *ATT, *FUSED, *DINV;
    bf16 *Phi, *Plo, *Hhi, *Hlo, *QKVhi, *QKVlo, *Ohi, *Olo, *CAThi, *CATlo, *VThi, *VTlo;
    bf16 *WGhi, *WGlo, *WAIhi, *WAIlo, *WAOhi, *WAOlo, *WGThi, *WGTlo, *WPhi, *WPlo;
    unsigned* ADJ; int* TOPK;
    cudaGetSymbolAddress((void**)&Sb, g_S);       cudaGetSymbolAddress((void**)&H, g_H);
    cudaGetSymbolAddress((void**)&XG, g_XG);      cudaGetSymbolAddress((void**)&GCN, g_GCN);
    cudaGetSymbolAddress((void**)&ATT, g_ATT);    cudaGetSymbolAddress((void**)&FUSED, g_FUSED);
    cudaGetSymbolAddress((void**)&DINV, g_dinv);  cudaGetSymbolAddress((void**)&ADJ, g_adj);
    cudaGetSymbolAddress((void**)&TOPK, g_topk);
    cudaGetSymbolAddress((void**)&Phi, g_Phi);    cudaGetSymbolAddress((void**)&Plo, g_Plo);
    cudaGetSymbolAddress((void**)&Hhi, g_Hhi);    cudaGetSymbolAddress((void**)&Hlo, g_Hlo);
    cudaGetSymbolAddress((void**)&QKVhi, g_QKVhi); cudaGetSymbolAddress((void**)&QKVlo, g_QKVlo);
    cudaGetSymbolAddress((void**)&Ohi, g_Ohi);    cudaGetSymbolAddress((void**)&Olo, g_Olo);
    cudaGetSymbolAddress((void**)&CAThi, g_CAThi); cudaGetSymbolAddress((void**)&CATlo, g_CATlo);
    cudaGetSymbolAddress((void**)&VThi, g_VThi);  cudaGetSymbolAddress((void**)&VTlo, g_VTlo);
    cudaGetSymbolAddress((void**)&WGhi, g_WGhi);  cudaGetSymbolAddress((void**)&WGlo, g_WGlo);
    cudaGetSymbolAddress((void**)&WAIhi, g_WAIhi); cudaGetSymbolAddress((void**)&WAIlo, g_WAIlo);
    cudaGetSymbolAddress((void**)&WAOhi, g_WAOhi); cudaGetSymbolAddress((void**)&WAOlo, g_WAOlo);
    cudaGetSymbolAddress((void**)&WGThi, g_WGThi); cudaGetSymbolAddress((void**)&WGTlo, g_WGTlo);
    cudaGetSymbolAddress((void**)&WPhi, g_WPhi);  cudaGetSymbolAddress((void**)&WPlo, g_WPlo);

    const int SM128 = 3 * (128*80 + 128*80);   // 61440
    const int SM96  = 3 * (128*80 +  96*80);   // 53760
    cudaFuncSetAttribute((const void*)hmma_gemm<128,4,0>, cudaFuncAttributeMaxDynamicSharedMemorySize, SM128);
    cudaFuncSetAttribute((const void*)hmma_gemm<128,4,1>, cudaFuncAttributeMaxDynamicSharedMemorySize, SM128);
    cudaFuncSetAttribute((const void*)hmma_gemm<128,4,2>, cudaFuncAttributeMaxDynamicSharedMemorySize, SM128);
    cudaFuncSetAttribute((const void*)hmma_gemm<96,3,2>,  cudaFuncAttributeMaxDynamicSharedMemorySize, SM96);

    const float att_scale = 1.0f / sqrtf((float)DH);
    dim3 tb(32, 8);

    // launches 0..4: memset, memcpy, splitH, tsplit(WAI l0), tsplit(WG l0)
    cudaMemsetAsync(ADJ, 0, (size_t)BS*32*sizeof(unsigned), 0);
    cudaMemcpyAsync(H, x, (size_t)BS*D*sizeof(float), cudaMemcpyDeviceToDevice, 0);
    split_kernel<<<BS*D/256, 256>>>(x, Hhi, Hlo, (size_t)BS*D);
    tsplit_kernel<<<dim3(3*D/32, D/32), tb>>>(ain_w, WAIhi, WAIlo, D, 3*D);
    tsplit_kernel<<<dim3(D/32, D/32), tb>>>(gcn_w, WGhi, WGlo, D, D);
    // launch 5 (ncu -s 5 -c 1 target): layer-0 QKV GEMM -> split bf16 out
    hmma_gemm<128,4,2><<<dim3(3*D/128, BS/128, 1), 256, SM128>>>(
        Hhi, Hlo, WAIhi, WAIlo, nullptr, D, D, D, 3*D,
        0,0,0,0,0,0, 1, 1.0f, ain_b, nullptr, nullptr, QKVhi, QKVlo);

    // --- graph construction: sim = x x^T per batch (fp32 SIMT — exact for top-k) ---
    dot_kernel<<<dim3(8, 8, B), 256>>>(x, Sb, D);
    topk_kernel<<<BS/256, 256>>>(Sb, TOPK);
    scatter_kernel<<<BS/256, 256>>>(TOPK, ADJ);
    deg_kernel<<<BS/256, 256>>>(ADJ, DINV);

    for (int l = 0; l < L_LAYERS; l++) {
        const float* gb  = gcn_b  + (size_t)l*D;
        const float* aib = ain_b  + (size_t)l*3*D;
        const float* aob = aout_b + (size_t)l*D;
        const float* gtb = gate_b + (size_t)l*D;

        if (l > 0) {
            tsplit_kernel<<<dim3(D/32, D/32), tb>>>(gcn_w + (size_t)l*D*D, WGhi, WGlo, D, D);
            tsplit_kernel<<<dim3(3*D/32, D/32), tb>>>(ain_w + (size_t)l*D*3*D, WAIhi, WAIlo, D, 3*D);
        }
        tsplit_kernel<<<dim3(D/32, D/32), tb>>>(aout_w + (size_t)l*D*D, WAOhi, WAOlo, D, D);
        tsplit_kernel<<<dim3(D/32, 2*D/32), tb>>>(gate_w + (size_t)l*2*D*D, WGThi, WGTlo, 2*D, D);

        // GCN branch: XG = H @ gcn_w (fp32 out), then sparse aggregation (+bias)
        hmma_gemm<128,4,0><<<dim3(D/128, BS/128, 1), 256, SM128>>>(
            Hhi, Hlo, WGhi, WGlo, XG, D, D, D, D,
            0,0,0,0,0,0, 1, 1.0f, nullptr, nullptr, nullptr, nullptr, nullptr);
        gcn_agg<<<BS, 256>>>(XG, ADJ, DINV, gb, GCN);

        // Attention branch: QKV (split-out epilogue); layer 0 already done pre-graph
        if (l > 0) {
            hmma_gemm<128,4,2><<<dim3(3*D/128, BS/128, 1), 256, SM128>>>(
                Hhi, Hlo, WAIhi, WAIlo, nullptr, D, D, D, 3*D,
                0,0,0,0,0,0, 1, 1.0f, aib, nullptr, nullptr, QKVhi, QKVlo);
        }
        vtsplit_kernel<<<dim3(S/32, DH/32, ZN), tb>>>(QKVhi, QKVlo, VThi, VTlo);

        // per-batch scores + softmax (32MB rotating buffer stays L2-resident)
        for (int b = 0; b < B; b++) {
            const size_t qo = (size_t)b*S*3*D;
            hmma_gemm<128,4,0><<<dim3(8, 8, HEADS), 256, SM128>>>(
                QKVhi + qo, QKVlo + qo, QKVhi + qo + D, QKVlo + qo + D,
                Sb, DH, 3*D, 3*D, S,
                0, DH, 0, DH, 0, (long long)S*S, HEADS,
                att_scale, nullptr, nullptr, nullptr, nullptr, nullptr);
            softmax_kernel<<<HEADS*S, 256>>>(Sb, Phi + (size_t)b*HEADS*S*S,
                                             Plo + (size_t)b*HEADS*S*S);
        }

        // O = P @ V (split-out epilogue; VT is [z][96][1024] K-major)
        hmma_gemm<96,3,2><<<dim3(1, 8, ZN), 192, SM96>>>(
            Phi, Plo, VThi, VTlo, nullptr, S, S, S, D,
            (long long)HEADS*S*S, (long long)S*S,
            (long long)HEADS*DH*S, (long long)DH*S,
            (long long)S*D, DH, HEADS,
            1.0f, nullptr, nullptr, nullptr, Ohi, Olo);

        // attn out-proj (fp32 out, needed by cat + gate epilogue)
        hmma_gemm<128,4,0><<<dim3(D/128, BS/128, 1), 256, SM128>>>(
            Ohi, Olo, WAOhi, WAOlo, ATT, D, D, D, D,
            0,0,0,0,0,0, 1, 1.0f, aob, nullptr, nullptr, nullptr, nullptr);

        // gate + fuse (fused sigmoid epilogue), then LN residual (+ split)
        cat_split_kernel<<<(int)((size_t)BS*2*D/256), 256>>>(GCN, ATT, CAThi, CATlo);
        hmma_gemm<128,4,1><<<dim3(D/128, BS/128, 1), 256, SM128>>>(
            CAThi, CATlo, WGThi, WGTlo, FUSED, 2*D, 2*D, 2*D, D,
            0,0,0,0,0,0, 1, 1.0f, gtb, GCN, ATT, nullptr, nullptr);
        ln_kernel<<<BS, 256>>>(FUSED, H, Hhi, Hlo, ln_s + (size_t)l*D, ln_b + (size_t)l*D);
    }

    // final projection -> d_out
    tsplit_kernel<<<dim3(D/32, D/32), tb>>>(proj_w, WPhi, WPlo, D, D);
    hmma_gemm<128,4,0><<<dim3(D/128, BS/128, 1), 256, SM128>>>(
        Hhi, Hlo, WPhi, WPlo, out, D, D, D, D,
        0,0,0,0,0,0, 1, 1.0f, proj_b, nullptr, nullptr, nullptr, nullptr);
}